// round 9
// baseline (speedup 1.0000x reference)
#include <cuda_runtime.h>
#include <cuda_fp16.h>
#include <math.h>

#define N_NODES 100000
#define N_EDGES 1600000
#define HID 64
#define CAP 96              // max degree bucket capacity (Poisson(16) tail << 96)

// Scratch (no cudaMalloc allowed).
__device__ __half2 g_h2[N_NODES * 32];          // 12.8 MB fp16 h (payload)
__device__ float   g_dotu[N_NODES];
__device__ float   g_dotv[N_NODES];
__device__ int     g_cnt[N_NODES];
__device__ int2    g_bucket[N_NODES * CAP];     // (src, w_bits) per edge

// ---------------------------------------------------------------------------
// f32x2 helpers (packed dual-fp32 FMA).
// ---------------------------------------------------------------------------
__device__ __forceinline__ unsigned long long pack2(float x, float y) {
    unsigned long long r;
    asm("mov.b64 %0, {%1, %2};" : "=l"(r) : "f"(x), "f"(y));
    return r;
}
__device__ __forceinline__ void unpack2(unsigned long long v, float& x, float& y) {
    asm("mov.b64 {%0, %1}, %2;" : "=f"(x), "=f"(y) : "l"(v));
}
__device__ __forceinline__ void fma2(unsigned long long& acc,
                                     unsigned long long a,
                                     unsigned long long b) {
    asm("fma.rn.f32x2 %0, %1, %2, %0;" : "+l"(acc) : "l"(a), "l"(b));
}

// ---------------------------------------------------------------------------
// K0: zero per-node counters.
// ---------------------------------------------------------------------------
__global__ void zero_kernel() {
    int i = blockIdx.x * blockDim.x + threadIdx.x;
    if (i < N_NODES) g_cnt[i] = 0;
}

// ---------------------------------------------------------------------------
// K1: h = feat @ W_in + b_in (f32x2 FFMA2), fused gate dot products.
// h stored to global as fp16 (half2); gate dots computed in fp32 from smem.
// ---------------------------------------------------------------------------
__global__ void input_gemm_kernel(const float* __restrict__ feat,
                                  const float* __restrict__ W_in,
                                  const float* __restrict__ b_in,
                                  const float* __restrict__ W_edge) {
    __shared__ __align__(16) float sW[HID * HID];
    __shared__ float sB[HID];
    __shared__ float sT[HID][HID + 1];
    __shared__ float sWu[HID], sWv[HID];

    int tid   = threadIdx.x;
    int node0 = blockIdx.x * 64;
    int n     = tid & 63;
    int q     = tid >> 6;

    for (int k = tid; k < HID * HID; k += 256) sW[k] = W_in[k];
    if (tid < HID) {
        sB[tid]  = b_in[tid];
        sWu[tid] = W_edge[tid];
        sWv[tid] = W_edge[HID + tid];
    }
    for (int idx = tid; idx < 64 * HID; idx += 256) {
        int nn = idx >> 6, k = idx & 63;
        int gn = node0 + nn;
        sT[k][nn] = (gn < N_NODES) ? feat[gn * HID + k] : 0.0f;
    }
    __syncthreads();

    unsigned long long acc[8];
    {
        int j0 = q * 16;
#pragma unroll
        for (int p = 0; p < 8; p++) acc[p] = pack2(sB[j0 + 2 * p], sB[j0 + 2 * p + 1]);
    }
    const ulonglong2* sW2 = (const ulonglong2*)sW;
#pragma unroll 8
    for (int k = 0; k < HID; k++) {
        float f = sT[k][n];
        unsigned long long ff = pack2(f, f);
        ulonglong2 wA = sW2[k * 16 + q * 4 + 0];
        ulonglong2 wB = sW2[k * 16 + q * 4 + 1];
        ulonglong2 wC = sW2[k * 16 + q * 4 + 2];
        ulonglong2 wD = sW2[k * 16 + q * 4 + 3];
        fma2(acc[0], ff, wA.x); fma2(acc[1], ff, wA.y);
        fma2(acc[2], ff, wB.x); fma2(acc[3], ff, wB.y);
        fma2(acc[4], ff, wC.x); fma2(acc[5], ff, wC.y);
        fma2(acc[6], ff, wD.x); fma2(acc[7], ff, wD.y);
    }
    __syncthreads();

    {
        int j0 = q * 16;
#pragma unroll
        for (int p = 0; p < 8; p++) {
            float x, y;
            unpack2(acc[p], x, y);
            sT[j0 + 2 * p][n]     = x;
            sT[j0 + 2 * p + 1][n] = y;
        }
    }
    __syncthreads();

    // coalesced fp16 h writes: half2 index jh covers feats 2jh, 2jh+1
    for (int idx = tid; idx < 64 * 32; idx += 256) {
        int nn = idx >> 5, jh = idx & 31;
        int gn = node0 + nn;
        if (gn < N_NODES)
            g_h2[gn * 32 + jh] = __floats2half2_rn(sT[2 * jh][nn], sT[2 * jh + 1][nn]);
    }
    // gate dot products (full fp32)
    if (tid < 64) {
        int gn = node0 + tid;
        if (gn < N_NODES) {
            float du = 0.f, dv = 0.f;
#pragma unroll
            for (int j = 0; j < HID; j++) {
                float hv = sT[j][tid];
                du = fmaf(hv, sWu[j], du);
                dv = fmaf(hv, sWv[j], dv);
            }
            g_dotu[gn] = du;
            g_dotv[gn] = dv;
        }
    }
}

// ---------------------------------------------------------------------------
// K2: bucket scatter WITH fused gate. 4 edges per thread.
// ---------------------------------------------------------------------------
__global__ void scatter_kernel(const int* __restrict__ src,
                               const int* __restrict__ dst,
                               const float* __restrict__ b_edge) {
    int t = blockIdx.x * blockDim.x + threadIdx.x;
    if (t * 4 >= N_EDGES) return;
    int4 s = ((const int4*)src)[t];
    int4 d = ((const int4*)dst)[t];
    float be = b_edge[0];

    float dux = g_dotu[s.x], duy = g_dotu[s.y], duz = g_dotu[s.z], duw = g_dotu[s.w];
    float dvx = g_dotv[d.x], dvy = g_dotv[d.y], dvz = g_dotv[d.z], dvw = g_dotv[d.w];

    float wx = 1.0f / (1.0f + __expf(-(dux + dvx + be)));
    float wy = 1.0f / (1.0f + __expf(-(duy + dvy + be)));
    float wz = 1.0f / (1.0f + __expf(-(duz + dvz + be)));
    float ww = 1.0f / (1.0f + __expf(-(duw + dvw + be)));

    int p;
    p = atomicAdd(&g_cnt[d.x], 1); g_bucket[d.x * CAP + p] = make_int2(s.x, __float_as_int(wx));
    p = atomicAdd(&g_cnt[d.y], 1); g_bucket[d.y * CAP + p] = make_int2(s.y, __float_as_int(wy));
    p = atomicAdd(&g_cnt[d.z], 1); g_bucket[d.z * CAP + p] = make_int2(s.z, __float_as_int(wz));
    p = atomicAdd(&g_cnt[d.w], 1); g_bucket[d.w * CAP + p] = make_int2(s.w, __float_as_int(ww));
}

// ---------------------------------------------------------------------------
// K3: atomic-free aggregate + fused output projection.
// One warp per node; 4 quarter-warps each own every 4th edge.
// Lane c loads ONE uint4 (8 fp16 feats 8c..8c+7) per edge: the 8 lanes of a
// quarter cover the whole 128B row in a single L1 wavefront.
// ---------------------------------------------------------------------------
__global__ void agg_out_kernel(const float* __restrict__ W_out,
                               const float* __restrict__ b_out,
                               float* __restrict__ out) {
    int lane = threadIdx.x & 31;
    long long n = (long long)(blockIdx.x * blockDim.x + threadIdx.x) >> 5;
    if (n >= N_NODES) return;

    int q = lane >> 3;
    int c = lane & 7;

    int start = (int)n * CAP;
    int cnt   = g_cnt[n];

    // packed fp32 accumulators: feats (8c..8c+1)(8c+2..3)(8c+4..5)(8c+6..7)
    unsigned long long A0 = 0, A1 = 0, A2 = 0, A3 = 0;
    const uint4* h16 = (const uint4*)g_h2;   // one uint4 = 8 halfs; row = 8 uint4

    int i   = start + q;
    int end = start + cnt;

    // 2-edge unrolled main loop (each quarter-warp strides by 4)
    for (; i + 4 < end; i += 8) {
        int2 eA = g_bucket[i];
        int2 eB = g_bucket[i + 4];
        uint4 rA = h16[(long long)eA.x * 8 + c];
        uint4 rB = h16[(long long)eB.x * 8 + c];
        float wA = __int_as_float(eA.y);
        float wB = __int_as_float(eB.y);
        unsigned long long wwA = pack2(wA, wA);
        unsigned long long wwB = pack2(wB, wB);
        float2 f;
        f = __half22float2(*(__half2*)&rA.x); fma2(A0, pack2(f.x, f.y), wwA);
        f = __half22float2(*(__half2*)&rA.y); fma2(A1, pack2(f.x, f.y), wwA);
        f = __half22float2(*(__half2*)&rA.z); fma2(A2, pack2(f.x, f.y), wwA);
        f = __half22float2(*(__half2*)&rA.w); fma2(A3, pack2(f.x, f.y), wwA);
        f = __half22float2(*(__half2*)&rB.x); fma2(A0, pack2(f.x, f.y), wwB);
        f = __half22float2(*(__half2*)&rB.y); fma2(A1, pack2(f.x, f.y), wwB);
        f = __half22float2(*(__half2*)&rB.z); fma2(A2, pack2(f.x, f.y), wwB);
        f = __half22float2(*(__half2*)&rB.w); fma2(A3, pack2(f.x, f.y), wwB);
    }
    // tail
    for (; i < end; i += 4) {
        int2 e = g_bucket[i];
        uint4 r = h16[(long long)e.x * 8 + c];
        float w = __int_as_float(e.y);
        unsigned long long ww = pack2(w, w);
        float2 f;
        f = __half22float2(*(__half2*)&r.x); fma2(A0, pack2(f.x, f.y), ww);
        f = __half22float2(*(__half2*)&r.y); fma2(A1, pack2(f.x, f.y), ww);
        f = __half22float2(*(__half2*)&r.z); fma2(A2, pack2(f.x, f.y), ww);
        f = __half22float2(*(__half2*)&r.w); fma2(A3, pack2(f.x, f.y), ww);
    }

    float4 a0, a1;   // a0 = feats 8c..8c+3, a1 = feats 8c+4..8c+7
    unpack2(A0, a0.x, a0.y); unpack2(A1, a0.z, a0.w);
    unpack2(A2, a1.x, a1.y); unpack2(A3, a1.z, a1.w);

    // reduce across the 4 quarters
#pragma unroll
    for (int off = 8; off <= 16; off <<= 1) {
        a0.x += __shfl_xor_sync(0xffffffffu, a0.x, off);
        a0.y += __shfl_xor_sync(0xffffffffu, a0.y, off);
        a0.z += __shfl_xor_sync(0xffffffffu, a0.z, off);
        a0.w += __shfl_xor_sync(0xffffffffu, a0.w, off);
        a1.x += __shfl_xor_sync(0xffffffffu, a1.x, off);
        a1.y += __shfl_xor_sync(0xffffffffu, a1.y, off);
        a1.z += __shfl_xor_sync(0xffffffffu, a1.z, off);
        a1.w += __shfl_xor_sync(0xffffffffu, a1.w, off);
    }
    if (cnt == 0) {                       // h_new = h when deg==0
        uint4 r = h16[n * 8 + c];
        float2 f;
        f = __half22float2(*(__half2*)&r.x); a0.x = f.x; a0.y = f.y;
        f = __half22float2(*(__half2*)&r.y); a0.z = f.x; a0.w = f.y;
        f = __half22float2(*(__half2*)&r.z); a1.x = f.x; a1.y = f.y;
        f = __half22float2(*(__half2*)&r.w); a1.z = f.x; a1.w = f.y;
    }

    // out = h_new @ W_out + b_out; lane c owns feats 8c..8c+7
    const float4* W4 = (const float4*)W_out;   // W4[f/2] = {W[f][0],W[f][1],W[f+1][0],W[f+1][1]}
    float4 wA = W4[c * 4 + 0], wB = W4[c * 4 + 1];
    float4 wC = W4[c * 4 + 2], wD = W4[c * 4 + 3];
    float s0 = a0.x * wA.x + a0.y * wA.z + a0.z * wB.x + a0.w * wB.z
             + a1.x * wC.x + a1.y * wC.z + a1.z * wD.x + a1.w * wD.z;
    float s1 = a0.x * wA.y + a0.y * wA.w + a0.z * wB.y + a0.w * wB.w
             + a1.x * wC.y + a1.y * wC.w + a1.z * wD.y + a1.w * wD.w;
#pragma unroll
    for (int off = 1; off <= 4; off <<= 1) {
        s0 += __shfl_xor_sync(0xffffffffu, s0, off);
        s1 += __shfl_xor_sync(0xffffffffu, s1, off);
    }
    if (lane == 0) {
        out[n * 2 + 0] = s0 + b_out[0];
        out[n * 2 + 1] = s1 + b_out[1];
    }
}

// ---------------------------------------------------------------------------
extern "C" void kernel_launch(void* const* d_in, const int* in_sizes, int n_in,
                              void* d_out, int out_size) {
    const float* feat   = (const float*)d_in[0];
    const int*   src    = (const int*)  d_in[1];
    const int*   dst    = (const int*)  d_in[2];
    const float* W_in   = (const float*)d_in[3];
    const float* b_in   = (const float*)d_in[4];
    const float* W_edge = (const float*)d_in[5];
    const float* b_edge = (const float*)d_in[6];
    const float* W_out  = (const float*)d_in[7];
    const float* b_out  = (const float*)d_in[8];
    float* out = (float*)d_out;

    zero_kernel<<<(N_NODES + 255) / 256, 256>>>();
    input_gemm_kernel<<<(N_NODES + 63) / 64, 256>>>(feat, W_in, b_in, W_edge);
    scatter_kernel<<<(N_EDGES / 4 + 255) / 256, 256>>>(src, dst, b_edge);
    agg_out_kernel<<<(int)((N_NODES * 32LL + 255) / 256), 256>>>(W_out, b_out, out);
}

// round 10
// speedup vs baseline: 1.2356x; 1.2356x over previous
#include <cuda_runtime.h>
#include <cuda_fp16.h>
#include <math.h>

#define N_NODES 100000
#define N_EDGES 1600000
#define HID 64
#define CAP 96              // max degree bucket capacity (Poisson(16) tail << 96)

// Scratch (no cudaMalloc allowed).
__device__ __half2 g_h2[N_NODES * 32];          // 12.8 MB fp16 h (payload)
__device__ float   g_dotu[N_NODES];
__device__ float   g_dotv[N_NODES];
__device__ int     g_cnt[N_NODES];
__device__ __align__(16) int2 g_bucket[N_NODES * CAP];  // (src, w_bits); row 16B-aligned

// ---------------------------------------------------------------------------
// f32x2 helpers (packed dual-fp32 FMA).
// ---------------------------------------------------------------------------
__device__ __forceinline__ unsigned long long pack2(float x, float y) {
    unsigned long long r;
    asm("mov.b64 %0, {%1, %2};" : "=l"(r) : "f"(x), "f"(y));
    return r;
}
__device__ __forceinline__ void unpack2(unsigned long long v, float& x, float& y) {
    asm("mov.b64 {%0, %1}, %2;" : "=f"(x), "=f"(y) : "l"(v));
}
__device__ __forceinline__ void fma2(unsigned long long& acc,
                                     unsigned long long a,
                                     unsigned long long b) {
    asm("fma.rn.f32x2 %0, %1, %2, %0;" : "+l"(acc) : "l"(a), "l"(b));
}

// ---------------------------------------------------------------------------
// K0: zero per-node counters.
// ---------------------------------------------------------------------------
__global__ void zero_kernel() {
    int i = blockIdx.x * blockDim.x + threadIdx.x;
    if (i < N_NODES) g_cnt[i] = 0;
}

// ---------------------------------------------------------------------------
// K1: h = feat @ W_in + b_in (f32x2 FFMA2), fused gate dot products.
// h stored fp16 (half2); gate dots fp32 from smem.
// ---------------------------------------------------------------------------
__global__ void input_gemm_kernel(const float* __restrict__ feat,
                                  const float* __restrict__ W_in,
                                  const float* __restrict__ b_in,
                                  const float* __restrict__ W_edge) {
    __shared__ __align__(16) float sW[HID * HID];
    __shared__ float sB[HID];
    __shared__ float sT[HID][HID + 1];
    __shared__ float sWu[HID], sWv[HID];

    int tid   = threadIdx.x;
    int node0 = blockIdx.x * 64;
    int n     = tid & 63;
    int q     = tid >> 6;

    for (int k = tid; k < HID * HID; k += 256) sW[k] = W_in[k];
    if (tid < HID) {
        sB[tid]  = b_in[tid];
        sWu[tid] = W_edge[tid];
        sWv[tid] = W_edge[HID + tid];
    }
    for (int idx = tid; idx < 64 * HID; idx += 256) {
        int nn = idx >> 6, k = idx & 63;
        int gn = node0 + nn;
        sT[k][nn] = (gn < N_NODES) ? feat[gn * HID + k] : 0.0f;
    }
    __syncthreads();

    unsigned long long acc[8];
    {
        int j0 = q * 16;
#pragma unroll
        for (int p = 0; p < 8; p++) acc[p] = pack2(sB[j0 + 2 * p], sB[j0 + 2 * p + 1]);
    }
    const ulonglong2* sW2 = (const ulonglong2*)sW;
#pragma unroll 8
    for (int k = 0; k < HID; k++) {
        float f = sT[k][n];
        unsigned long long ff = pack2(f, f);
        ulonglong2 wA = sW2[k * 16 + q * 4 + 0];
        ulonglong2 wB = sW2[k * 16 + q * 4 + 1];
        ulonglong2 wC = sW2[k * 16 + q * 4 + 2];
        ulonglong2 wD = sW2[k * 16 + q * 4 + 3];
        fma2(acc[0], ff, wA.x); fma2(acc[1], ff, wA.y);
        fma2(acc[2], ff, wB.x); fma2(acc[3], ff, wB.y);
        fma2(acc[4], ff, wC.x); fma2(acc[5], ff, wC.y);
        fma2(acc[6], ff, wD.x); fma2(acc[7], ff, wD.y);
    }
    __syncthreads();

    {
        int j0 = q * 16;
#pragma unroll
        for (int p = 0; p < 8; p++) {
            float x, y;
            unpack2(acc[p], x, y);
            sT[j0 + 2 * p][n]     = x;
            sT[j0 + 2 * p + 1][n] = y;
        }
    }
    __syncthreads();

    // coalesced fp16 h writes
    for (int idx = tid; idx < 64 * 32; idx += 256) {
        int nn = idx >> 5, jh = idx & 31;
        int gn = node0 + nn;
        if (gn < N_NODES)
            g_h2[gn * 32 + jh] = __floats2half2_rn(sT[2 * jh][nn], sT[2 * jh + 1][nn]);
    }
    // gate dot products (fp32)
    if (tid < 64) {
        int gn = node0 + tid;
        if (gn < N_NODES) {
            float du = 0.f, dv = 0.f;
#pragma unroll
            for (int j = 0; j < HID; j++) {
                float hv = sT[j][tid];
                du = fmaf(hv, sWu[j], du);
                dv = fmaf(hv, sWv[j], dv);
            }
            g_dotu[gn] = du;
            g_dotv[gn] = dv;
        }
    }
}

// ---------------------------------------------------------------------------
// K2: bucket scatter WITH fused gate. 4 edges per thread.
// ---------------------------------------------------------------------------
__global__ void scatter_kernel(const int* __restrict__ src,
                               const int* __restrict__ dst,
                               const float* __restrict__ b_edge) {
    int t = blockIdx.x * blockDim.x + threadIdx.x;
    if (t * 4 >= N_EDGES) return;
    int4 s = ((const int4*)src)[t];
    int4 d = ((const int4*)dst)[t];
    float be = b_edge[0];

    float dux = g_dotu[s.x], duy = g_dotu[s.y], duz = g_dotu[s.z], duw = g_dotu[s.w];
    float dvx = g_dotv[d.x], dvy = g_dotv[d.y], dvz = g_dotv[d.z], dvw = g_dotv[d.w];

    float wx = 1.0f / (1.0f + __expf(-(dux + dvx + be)));
    float wy = 1.0f / (1.0f + __expf(-(duy + dvy + be)));
    float wz = 1.0f / (1.0f + __expf(-(duz + dvz + be)));
    float ww = 1.0f / (1.0f + __expf(-(duw + dvw + be)));

    int p;
    p = atomicAdd(&g_cnt[d.x], 1); g_bucket[d.x * CAP + p] = make_int2(s.x, __float_as_int(wx));
    p = atomicAdd(&g_cnt[d.y], 1); g_bucket[d.y * CAP + p] = make_int2(s.y, __float_as_int(wy));
    p = atomicAdd(&g_cnt[d.z], 1); g_bucket[d.z * CAP + p] = make_int2(s.z, __float_as_int(wz));
    p = atomicAdd(&g_cnt[d.w], 1); g_bucket[d.w * CAP + p] = make_int2(s.w, __float_as_int(ww));
}

// ---------------------------------------------------------------------------
// K3: atomic-free aggregate + fused output projection.
// ONE NODE PER QUARTER-WARP (8 lanes). Lane c owns fp16 feats 8c..8c+7 as a
// single uint4 (quarter covers the 128B row in one L1 wavefront). Full degree
// loop per quarter — no cross-quarter reduction; epilogue is a 3-stage 8-lane
// reduce for the 2-class projection only. Unroll x2 via int4 bucket loads.
// ---------------------------------------------------------------------------
__global__ void __launch_bounds__(256, 8)
agg_out_kernel(const float* __restrict__ W_out,
               const float* __restrict__ b_out,
               float* __restrict__ out) {
    int lane = threadIdx.x & 31;
    int warp_global = (blockIdx.x * blockDim.x + threadIdx.x) >> 5;
    int q = lane >> 3;
    int c = lane & 7;
    int n = warp_global * 4 + q;          // node owned by this quarter
    if (n >= N_NODES) return;

    int start = n * CAP;
    int cnt   = g_cnt[n];
    int end   = start + cnt;

    // fp32 packed accumulators for feats (8c..8c+1)(+2..3)(+4..5)(+6..7)
    unsigned long long A0 = 0, A1 = 0, A2 = 0, A3 = 0;
    const uint4* h16 = (const uint4*)g_h2;   // row = 8 uint4

    int i = start;
    // 2-edge unrolled loop: one int4 = two (src,w) bucket entries
    for (; i + 1 < end; i += 2) {
        int4 e2 = *(const int4*)&g_bucket[i];   // (s0, w0, s1, w1)
        uint4 r0 = h16[(long long)e2.x * 8 + c];
        uint4 r1 = h16[(long long)e2.z * 8 + c];
        float w0 = __int_as_float(e2.y);
        float w1 = __int_as_float(e2.w);
        unsigned long long ww0 = pack2(w0, w0);
        unsigned long long ww1 = pack2(w1, w1);
        float2 f;
        f = __half22float2(*(__half2*)&r0.x); fma2(A0, pack2(f.x, f.y), ww0);
        f = __half22float2(*(__half2*)&r0.y); fma2(A1, pack2(f.x, f.y), ww0);
        f = __half22float2(*(__half2*)&r0.z); fma2(A2, pack2(f.x, f.y), ww0);
        f = __half22float2(*(__half2*)&r0.w); fma2(A3, pack2(f.x, f.y), ww0);
        f = __half22float2(*(__half2*)&r1.x); fma2(A0, pack2(f.x, f.y), ww1);
        f = __half22float2(*(__half2*)&r1.y); fma2(A1, pack2(f.x, f.y), ww1);
        f = __half22float2(*(__half2*)&r1.z); fma2(A2, pack2(f.x, f.y), ww1);
        f = __half22float2(*(__half2*)&r1.w); fma2(A3, pack2(f.x, f.y), ww1);
    }
    if (i < end) {
        int2 e = g_bucket[i];
        uint4 r = h16[(long long)e.x * 8 + c];
        float w = __int_as_float(e.y);
        unsigned long long ww = pack2(w, w);
        float2 f;
        f = __half22float2(*(__half2*)&r.x); fma2(A0, pack2(f.x, f.y), ww);
        f = __half22float2(*(__half2*)&r.y); fma2(A1, pack2(f.x, f.y), ww);
        f = __half22float2(*(__half2*)&r.z); fma2(A2, pack2(f.x, f.y), ww);
        f = __half22float2(*(__half2*)&r.w); fma2(A3, pack2(f.x, f.y), ww);
    }

    float4 a0, a1;   // a0 = feats 8c..8c+3, a1 = feats 8c+4..8c+7
    unpack2(A0, a0.x, a0.y); unpack2(A1, a0.z, a0.w);
    unpack2(A2, a1.x, a1.y); unpack2(A3, a1.z, a1.w);

    if (cnt == 0) {                       // h_new = h when deg==0
        uint4 r = h16[(long long)n * 8 + c];
        float2 f;
        f = __half22float2(*(__half2*)&r.x); a0.x = f.x; a0.y = f.y;
        f = __half22float2(*(__half2*)&r.y); a0.z = f.x; a0.w = f.y;
        f = __half22float2(*(__half2*)&r.z); a1.x = f.x; a1.y = f.y;
        f = __half22float2(*(__half2*)&r.w); a1.z = f.x; a1.w = f.y;
    }

    // out = h_new @ W_out + b_out; lane c owns feats 8c..8c+7
    const float4* W4 = (const float4*)W_out;   // W4[f/2] = {W[f][0],W[f][1],W[f+1][0],W[f+1][1]}
    float4 wA = W4[c * 4 + 0], wB = W4[c * 4 + 1];
    float4 wC = W4[c * 4 + 2], wD = W4[c * 4 + 3];
    float s0 = a0.x * wA.x + a0.y * wA.z + a0.z * wB.x + a0.w * wB.z
             + a1.x * wC.x + a1.y * wC.z + a1.z * wD.x + a1.w * wD.z;
    float s1 = a0.x * wA.y + a0.y * wA.w + a0.z * wB.y + a0.w * wB.w
             + a1.x * wC.y + a1.y * wC.w + a1.z * wD.y + a1.w * wD.w;
    // reduce within the 8-lane quarter
#pragma unroll
    for (int off = 1; off <= 4; off <<= 1) {
        s0 += __shfl_xor_sync(0xffffffffu, s0, off);
        s1 += __shfl_xor_sync(0xffffffffu, s1, off);
    }
    if (c == 0) {
        out[n * 2 + 0] = s0 + b_out[0];
        out[n * 2 + 1] = s1 + b_out[1];
    }
}

// ---------------------------------------------------------------------------
extern "C" void kernel_launch(void* const* d_in, const int* in_sizes, int n_in,
                              void* d_out, int out_size) {
    const float* feat   = (const float*)d_in[0];
    const int*   src    = (const int*)  d_in[1];
    const int*   dst    = (const int*)  d_in[2];
    const float* W_in   = (const float*)d_in[3];
    const float* b_in   = (const float*)d_in[4];
    const float* W_edge = (const float*)d_in[5];
    const float* b_edge = (const float*)d_in[6];
    const float* W_out  = (const float*)d_in[7];
    const float* b_out  = (const float*)d_in[8];
    float* out = (float*)d_out;

    zero_kernel<<<(N_NODES + 255) / 256, 256>>>();
    input_gemm_kernel<<<(N_NODES + 63) / 64, 256>>>(feat, W_in, b_in, W_edge);
    scatter_kernel<<<(N_EDGES / 4 + 255) / 256, 256>>>(src, dst, b_edge);
    // one node per quarter-warp: 100000 nodes / (4 nodes/warp * 8 warps/block) = 3125 blocks
    agg_out_kernel<<<3125, 256>>>(W_out, b_out, out);
}

// round 11
// speedup vs baseline: 1.2783x; 1.0345x over previous
#include <cuda_runtime.h>
#include <cuda_fp16.h>
#include <math.h>

#define N_NODES 100000
#define N_EDGES 1600000
#define HID 64
#define CAP 96              // max degree bucket capacity (Poisson(16) tail << 96)
#define W_INV (1.0f / 32767.0f)

// Scratch (no cudaMalloc allowed).
__device__ __half2  g_h2[N_NODES * 32];         // 12.8 MB fp16 h (payload)
__device__ float    g_dotu[N_NODES];
__device__ float    g_dotv[N_NODES];
__device__ int      g_cnt[N_NODES];
__device__ __align__(16) unsigned int g_bucket[N_NODES * CAP];  // (src<<15 | w15)

// ---------------------------------------------------------------------------
// f32x2 helpers (packed dual-fp32 FMA).
// ---------------------------------------------------------------------------
__device__ __forceinline__ unsigned long long pack2(float x, float y) {
    unsigned long long r;
    asm("mov.b64 %0, {%1, %2};" : "=l"(r) : "f"(x), "f"(y));
    return r;
}
__device__ __forceinline__ void unpack2(unsigned long long v, float& x, float& y) {
    asm("mov.b64 {%0, %1}, %2;" : "=f"(x), "=f"(y) : "l"(v));
}
__device__ __forceinline__ void fma2(unsigned long long& acc,
                                     unsigned long long a,
                                     unsigned long long b) {
    asm("fma.rn.f32x2 %0, %1, %2, %0;" : "+l"(acc) : "l"(a), "l"(b));
}

// ---------------------------------------------------------------------------
// K0: zero per-node counters.
// ---------------------------------------------------------------------------
__global__ void zero_kernel() {
    int i = blockIdx.x * blockDim.x + threadIdx.x;
    if (i < N_NODES) g_cnt[i] = 0;
}

// ---------------------------------------------------------------------------
// K1: h = feat @ W_in + b_in (f32x2 FFMA2), fused gate dot products.
// Epilogue: per-thread 16-feat partial dots from REGISTERS + 4-way smem reduce.
// ---------------------------------------------------------------------------
__global__ void input_gemm_kernel(const float* __restrict__ feat,
                                  const float* __restrict__ W_in,
                                  const float* __restrict__ b_in,
                                  const float* __restrict__ W_edge) {
    __shared__ __align__(16) float sW[HID * HID];
    __shared__ float sB[HID];
    __shared__ float sT[HID][HID + 1];
    __shared__ float sWu[HID], sWv[HID];
    __shared__ float sDu[4][HID], sDv[4][HID];

    int tid   = threadIdx.x;
    int node0 = blockIdx.x * 64;
    int n     = tid & 63;
    int q     = tid >> 6;
    int j0    = q * 16;

    for (int k = tid; k < HID * HID; k += 256) sW[k] = W_in[k];
    if (tid < HID) {
        sB[tid]  = b_in[tid];
        sWu[tid] = W_edge[tid];
        sWv[tid] = W_edge[HID + tid];
    }
    for (int idx = tid; idx < 64 * HID; idx += 256) {
        int nn = idx >> 6, k = idx & 63;
        int gn = node0 + nn;
        sT[k][nn] = (gn < N_NODES) ? feat[gn * HID + k] : 0.0f;
    }
    __syncthreads();

    unsigned long long acc[8];
#pragma unroll
    for (int p = 0; p < 8; p++) acc[p] = pack2(sB[j0 + 2 * p], sB[j0 + 2 * p + 1]);

    const ulonglong2* sW2 = (const ulonglong2*)sW;
#pragma unroll 8
    for (int k = 0; k < HID; k++) {
        float f = sT[k][n];
        unsigned long long ff = pack2(f, f);
        ulonglong2 wA = sW2[k * 16 + q * 4 + 0];
        ulonglong2 wB = sW2[k * 16 + q * 4 + 1];
        ulonglong2 wC = sW2[k * 16 + q * 4 + 2];
        ulonglong2 wD = sW2[k * 16 + q * 4 + 3];
        fma2(acc[0], ff, wA.x); fma2(acc[1], ff, wA.y);
        fma2(acc[2], ff, wB.x); fma2(acc[3], ff, wB.y);
        fma2(acc[4], ff, wC.x); fma2(acc[5], ff, wC.y);
        fma2(acc[6], ff, wD.x); fma2(acc[7], ff, wD.y);
    }

    // per-thread partial gate dots from registers
    float du_p = 0.f, dv_p = 0.f;
    float hx[16];
#pragma unroll
    for (int p = 0; p < 8; p++) unpack2(acc[p], hx[2 * p], hx[2 * p + 1]);
#pragma unroll
    for (int j = 0; j < 16; j++) {
        du_p = fmaf(hx[j], sWu[j0 + j], du_p);
        dv_p = fmaf(hx[j], sWv[j0 + j], dv_p);
    }
    sDu[q][n] = du_p;
    sDv[q][n] = dv_p;

    __syncthreads();   // sT free to be overwritten (all reads done)

#pragma unroll
    for (int p = 0; p < 8; p++) {
        sT[j0 + 2 * p][n]     = hx[2 * p];
        sT[j0 + 2 * p + 1][n] = hx[2 * p + 1];
    }
    __syncthreads();

    // coalesced fp16 h writes
    for (int idx = tid; idx < 64 * 32; idx += 256) {
        int nn = idx >> 5, jh = idx & 31;
        int gn = node0 + nn;
        if (gn < N_NODES)
            g_h2[gn * 32 + jh] = __floats2half2_rn(sT[2 * jh][nn], sT[2 * jh + 1][nn]);
    }
    if (tid < 64) {
        int gn = node0 + tid;
        if (gn < N_NODES) {
            g_dotu[gn] = sDu[0][tid] + sDu[1][tid] + sDu[2][tid] + sDu[3][tid];
            g_dotv[gn] = sDv[0][tid] + sDv[1][tid] + sDv[2][tid] + sDv[3][tid];
        }
    }
}

// ---------------------------------------------------------------------------
// K2: bucket scatter with fused gate, 8 edges per thread (MLP 16), packed
// 4-byte entries: (src << 15) | round(w * 32767).
// ---------------------------------------------------------------------------
__global__ void scatter_kernel(const int* __restrict__ src,
                               const int* __restrict__ dst,
                               const float* __restrict__ b_edge) {
    int t = blockIdx.x * blockDim.x + threadIdx.x;
    if (t * 8 >= N_EDGES) return;
    const int4* s4 = (const int4*)src;
    const int4* d4 = (const int4*)dst;
    int4 sA = s4[2 * t], sB = s4[2 * t + 1];
    int4 dA = d4[2 * t], dB = d4[2 * t + 1];
    float be = b_edge[0];

    // issue all 16 random scalar loads first
    float u0 = g_dotu[sA.x], u1 = g_dotu[sA.y], u2 = g_dotu[sA.z], u3 = g_dotu[sA.w];
    float u4 = g_dotu[sB.x], u5 = g_dotu[sB.y], u6 = g_dotu[sB.z], u7 = g_dotu[sB.w];
    float v0 = g_dotv[dA.x], v1 = g_dotv[dA.y], v2 = g_dotv[dA.z], v3 = g_dotv[dA.w];
    float v4 = g_dotv[dB.x], v5 = g_dotv[dB.y], v6 = g_dotv[dB.z], v7 = g_dotv[dB.w];

    #define GATE(u, v) (1.0f / (1.0f + __expf(-((u) + (v) + be))))
    unsigned int w0 = (unsigned int)(GATE(u0, v0) * 32767.0f + 0.5f);
    unsigned int w1 = (unsigned int)(GATE(u1, v1) * 32767.0f + 0.5f);
    unsigned int w2 = (unsigned int)(GATE(u2, v2) * 32767.0f + 0.5f);
    unsigned int w3 = (unsigned int)(GATE(u3, v3) * 32767.0f + 0.5f);
    unsigned int w4 = (unsigned int)(GATE(u4, v4) * 32767.0f + 0.5f);
    unsigned int w5 = (unsigned int)(GATE(u5, v5) * 32767.0f + 0.5f);
    unsigned int w6 = (unsigned int)(GATE(u6, v6) * 32767.0f + 0.5f);
    unsigned int w7 = (unsigned int)(GATE(u7, v7) * 32767.0f + 0.5f);
    #undef GATE

    int p;
    p = atomicAdd(&g_cnt[dA.x], 1); g_bucket[dA.x * CAP + p] = ((unsigned)sA.x << 15) | w0;
    p = atomicAdd(&g_cnt[dA.y], 1); g_bucket[dA.y * CAP + p] = ((unsigned)sA.y << 15) | w1;
    p = atomicAdd(&g_cnt[dA.z], 1); g_bucket[dA.z * CAP + p] = ((unsigned)sA.z << 15) | w2;
    p = atomicAdd(&g_cnt[dA.w], 1); g_bucket[dA.w * CAP + p] = ((unsigned)sA.w << 15) | w3;
    p = atomicAdd(&g_cnt[dB.x], 1); g_bucket[dB.x * CAP + p] = ((unsigned)sB.x << 15) | w4;
    p = atomicAdd(&g_cnt[dB.y], 1); g_bucket[dB.y * CAP + p] = ((unsigned)sB.y << 15) | w5;
    p = atomicAdd(&g_cnt[dB.z], 1); g_bucket[dB.z * CAP + p] = ((unsigned)sB.z << 15) | w6;
    p = atomicAdd(&g_cnt[dB.w], 1); g_bucket[dB.w * CAP + p] = ((unsigned)sB.w << 15) | w7;
}

// ---------------------------------------------------------------------------
// K3: atomic-free aggregate + fused output projection.
// One node per quarter-warp (8 lanes); lane c owns fp16 feats 8c..8c+7.
// 4-edge unrolled via one uint4 bucket load (4 packed entries) -> MLP 5.
// ---------------------------------------------------------------------------
__global__ void __launch_bounds__(256, 6)
agg_out_kernel(const float* __restrict__ W_out,
               const float* __restrict__ b_out,
               float* __restrict__ out) {
    int lane = threadIdx.x & 31;
    int warp_global = (blockIdx.x * blockDim.x + threadIdx.x) >> 5;
    int q = lane >> 3;
    int c = lane & 7;
    int n = warp_global * 4 + q;
    if (n >= N_NODES) return;

    int start = n * CAP;                  // multiple of 4 -> uint4 aligned
    int cnt   = g_cnt[n];
    int end   = start + cnt;

    unsigned long long A0 = 0, A1 = 0, A2 = 0, A3 = 0;
    const uint4* h16 = (const uint4*)g_h2;   // row = 8 uint4

    int i = start;
    for (; i + 3 < end; i += 4) {
        uint4 e = *(const uint4*)&g_bucket[i];
        unsigned sx = e.x >> 15, sy = e.y >> 15, sz = e.z >> 15, sw = e.w >> 15;
        uint4 r0 = h16[(long long)sx * 8 + c];
        uint4 r1 = h16[(long long)sy * 8 + c];
        uint4 r2 = h16[(long long)sz * 8 + c];
        uint4 r3 = h16[(long long)sw * 8 + c];
        float w0 = (float)(e.x & 0x7fffu) * W_INV;
        float w1 = (float)(e.y & 0x7fffu) * W_INV;
        float w2 = (float)(e.z & 0x7fffu) * W_INV;
        float w3 = (float)(e.w & 0x7fffu) * W_INV;
        unsigned long long ww;
        float2 f;
        ww = pack2(w0, w0);
        f = __half22float2(*(__half2*)&r0.x); fma2(A0, pack2(f.x, f.y), ww);
        f = __half22float2(*(__half2*)&r0.y); fma2(A1, pack2(f.x, f.y), ww);
        f = __half22float2(*(__half2*)&r0.z); fma2(A2, pack2(f.x, f.y), ww);
        f = __half22float2(*(__half2*)&r0.w); fma2(A3, pack2(f.x, f.y), ww);
        ww = pack2(w1, w1);
        f = __half22float2(*(__half2*)&r1.x); fma2(A0, pack2(f.x, f.y), ww);
        f = __half22float2(*(__half2*)&r1.y); fma2(A1, pack2(f.x, f.y), ww);
        f = __half22float2(*(__half2*)&r1.z); fma2(A2, pack2(f.x, f.y), ww);
        f = __half22float2(*(__half2*)&r1.w); fma2(A3, pack2(f.x, f.y), ww);
        ww = pack2(w2, w2);
        f = __half22float2(*(__half2*)&r2.x); fma2(A0, pack2(f.x, f.y), ww);
        f = __half22float2(*(__half2*)&r2.y); fma2(A1, pack2(f.x, f.y), ww);
        f = __half22float2(*(__half2*)&r2.z); fma2(A2, pack2(f.x, f.y), ww);
        f = __half22float2(*(__half2*)&r2.w); fma2(A3, pack2(f.x, f.y), ww);
        ww = pack2(w3, w3);
        f = __half22float2(*(__half2*)&r3.x); fma2(A0, pack2(f.x, f.y), ww);
        f = __half22float2(*(__half2*)&r3.y); fma2(A1, pack2(f.x, f.y), ww);
        f = __half22float2(*(__half2*)&r3.z); fma2(A2, pack2(f.x, f.y), ww);
        f = __half22float2(*(__half2*)&r3.w); fma2(A3, pack2(f.x, f.y), ww);
    }
    for (; i < end; i++) {
        unsigned e = g_bucket[i];
        unsigned s = e >> 15;
        float w = (float)(e & 0x7fffu) * W_INV;
        uint4 r = h16[(long long)s * 8 + c];
        unsigned long long ww = pack2(w, w);
        float2 f;
        f = __half22float2(*(__half2*)&r.x); fma2(A0, pack2(f.x, f.y), ww);
        f = __half22float2(*(__half2*)&r.y); fma2(A1, pack2(f.x, f.y), ww);
        f = __half22float2(*(__half2*)&r.z); fma2(A2, pack2(f.x, f.y), ww);
        f = __half22float2(*(__half2*)&r.w); fma2(A3, pack2(f.x, f.y), ww);
    }

    float4 a0, a1;   // a0 = feats 8c..8c+3, a1 = feats 8c+4..8c+7
    unpack2(A0, a0.x, a0.y); unpack2(A1, a0.z, a0.w);
    unpack2(A2, a1.x, a1.y); unpack2(A3, a1.z, a1.w);

    if (cnt == 0) {                       // h_new = h when deg==0
        uint4 r = h16[(long long)n * 8 + c];
        float2 f;
        f = __half22float2(*(__half2*)&r.x); a0.x = f.x; a0.y = f.y;
        f = __half22float2(*(__half2*)&r.y); a0.z = f.x; a0.w = f.y;
        f = __half22float2(*(__half2*)&r.z); a1.x = f.x; a1.y = f.y;
        f = __half22float2(*(__half2*)&r.w); a1.z = f.x; a1.w = f.y;
    }

    // out = h_new @ W_out + b_out; lane c owns feats 8c..8c+7
    const float4* W4 = (const float4*)W_out;
    float4 wA = W4[c * 4 + 0], wB = W4[c * 4 + 1];
    float4 wC = W4[c * 4 + 2], wD = W4[c * 4 + 3];
    float s0 = a0.x * wA.x + a0.y * wA.z + a0.z * wB.x + a0.w * wB.z
             + a1.x * wC.x + a1.y * wC.z + a1.z * wD.x + a1.w * wD.z;
    float s1 = a0.x * wA.y + a0.y * wA.w + a0.z * wB.y + a0.w * wB.w
             + a1.x * wC.y + a1.y * wC.w + a1.z * wD.y + a1.w * wD.w;
#pragma unroll
    for (int off = 1; off <= 4; off <<= 1) {
        s0 += __shfl_xor_sync(0xffffffffu, s0, off);
        s1 += __shfl_xor_sync(0xffffffffu, s1, off);
    }
    if (c == 0) {
        out[n * 2 + 0] = s0 + b_out[0];
        out[n * 2 + 1] = s1 + b_out[1];
    }
}

// ---------------------------------------------------------------------------
extern "C" void kernel_launch(void* const* d_in, const int* in_sizes, int n_in,
                              void* d_out, int out_size) {
    const float* feat   = (const float*)d_in[0];
    const int*   src    = (const int*)  d_in[1];
    const int*   dst    = (const int*)  d_in[2];
    const float* W_in   = (const float*)d_in[3];
    const float* b_in   = (const float*)d_in[4];
    const float* W_edge = (const float*)d_in[5];
    const float* b_edge = (const float*)d_in[6];
    const float* W_out  = (const float*)d_in[7];
    const float* b_out  = (const float*)d_in[8];
    float* out = (float*)d_out;

    zero_kernel<<<(N_NODES + 255) / 256, 256>>>();
    input_gemm_kernel<<<(N_NODES + 63) / 64, 256>>>(feat, W_in, b_in, W_edge);
    scatter_kernel<<<(N_EDGES / 8 + 255) / 256, 256>>>(src, dst, b_edge);
    agg_out_kernel<<<3125, 256>>>(W_out, b_out, out);
}

// round 12
// speedup vs baseline: 1.6444x; 1.2864x over previous
#include <cuda_runtime.h>
#include <math.h>

#define N_NODES 100000
#define N_EDGES 1600000
#define HID 64
#define CAP 96              // max degree bucket capacity (Poisson(16) tail << 96)

// Scratch (no cudaMalloc allowed).
__device__ float4 g_node[N_NODES];              // (dotu, dotv, z0, z1) per node, 1.6 MB
__device__ int    g_cnt[N_NODES];
__device__ __align__(16) float2 g_bucket[N_NODES * CAP];  // (w*z0, w*z1) per edge

// ---------------------------------------------------------------------------
// f32x2 helpers (packed dual-fp32 FMA).
// ---------------------------------------------------------------------------
__device__ __forceinline__ unsigned long long pack2(float x, float y) {
    unsigned long long r;
    asm("mov.b64 %0, {%1, %2};" : "=l"(r) : "f"(x), "f"(y));
    return r;
}
__device__ __forceinline__ void unpack2(unsigned long long v, float& x, float& y) {
    asm("mov.b64 {%0, %1}, %2;" : "=f"(x), "=f"(y) : "l"(v));
}
__device__ __forceinline__ void fma2(unsigned long long& acc,
                                     unsigned long long a,
                                     unsigned long long b) {
    asm("fma.rn.f32x2 %0, %1, %2, %0;" : "+l"(acc) : "l"(a), "l"(b));
}

// ---------------------------------------------------------------------------
// K0: zero per-node counters.
// ---------------------------------------------------------------------------
__global__ void zero_kernel() {
    int i = blockIdx.x * blockDim.x + threadIdx.x;
    if (i < N_NODES) g_cnt[i] = 0;
}

// ---------------------------------------------------------------------------
// K1: h = feat @ W_in + b_in (f32x2 FFMA2, h stays in REGISTERS), fused with
// the four per-node linear functionals the rest of the net needs:
//   dotu = h·W_edge[0:64], dotv = h·W_edge[64:128],
//   z0 = h·W_out[:,0], z1 = h·W_out[:,1]
// Output: g_node[n] = (dotu, dotv, z0, z1). h is never written to global.
// ---------------------------------------------------------------------------
__global__ void input_gemm_kernel(const float* __restrict__ feat,
                                  const float* __restrict__ W_in,
                                  const float* __restrict__ b_in,
                                  const float* __restrict__ W_edge,
                                  const float* __restrict__ W_out) {
    __shared__ __align__(16) float sW[HID * HID];   // W_in, 16 KB
    __shared__ float sB[HID];
    __shared__ float sT[HID][HID + 1];              // transposed feat tile
    __shared__ float sWu[HID], sWv[HID], sWo0[HID], sWo1[HID];
    __shared__ float sP[4][HID][4];                 // per-q partials (du,dv,z0,z1)

    int tid   = threadIdx.x;
    int node0 = blockIdx.x * 64;
    int n     = tid & 63;
    int q     = tid >> 6;
    int j0    = q * 16;

    for (int k = tid; k < HID * HID; k += 256) sW[k] = W_in[k];
    if (tid < HID) {
        sB[tid]   = b_in[tid];
        sWu[tid]  = W_edge[tid];
        sWv[tid]  = W_edge[HID + tid];
        sWo0[tid] = W_out[2 * tid];
        sWo1[tid] = W_out[2 * tid + 1];
    }
    for (int idx = tid; idx < 64 * HID; idx += 256) {
        int nn = idx >> 6, k = idx & 63;
        int gn = node0 + nn;
        sT[k][nn] = (gn < N_NODES) ? feat[gn * HID + k] : 0.0f;
    }
    __syncthreads();

    unsigned long long acc[8];
#pragma unroll
    for (int p = 0; p < 8; p++) acc[p] = pack2(sB[j0 + 2 * p], sB[j0 + 2 * p + 1]);

    const ulonglong2* sW2 = (const ulonglong2*)sW;
#pragma unroll 8
    for (int k = 0; k < HID; k++) {
        float f = sT[k][n];
        unsigned long long ff = pack2(f, f);
        ulonglong2 wA = sW2[k * 16 + q * 4 + 0];
        ulonglong2 wB = sW2[k * 16 + q * 4 + 1];
        ulonglong2 wC = sW2[k * 16 + q * 4 + 2];
        ulonglong2 wD = sW2[k * 16 + q * 4 + 3];
        fma2(acc[0], ff, wA.x); fma2(acc[1], ff, wA.y);
        fma2(acc[2], ff, wB.x); fma2(acc[3], ff, wB.y);
        fma2(acc[4], ff, wC.x); fma2(acc[5], ff, wC.y);
        fma2(acc[6], ff, wD.x); fma2(acc[7], ff, wD.y);
    }

    // per-thread partial functionals from registers
    float hx[16];
#pragma unroll
    for (int p = 0; p < 8; p++) unpack2(acc[p], hx[2 * p], hx[2 * p + 1]);
    float du = 0.f, dv = 0.f, z0 = 0.f, z1 = 0.f;
#pragma unroll
    for (int j = 0; j < 16; j++) {
        float hv = hx[j];
        du = fmaf(hv, sWu[j0 + j],  du);
        dv = fmaf(hv, sWv[j0 + j],  dv);
        z0 = fmaf(hv, sWo0[j0 + j], z0);
        z1 = fmaf(hv, sWo1[j0 + j], z1);
    }
    sP[q][n][0] = du; sP[q][n][1] = dv; sP[q][n][2] = z0; sP[q][n][3] = z1;
    __syncthreads();

    if (tid < 64) {
        int gn = node0 + tid;
        if (gn < N_NODES) {
            float4 r;
            r.x = sP[0][tid][0] + sP[1][tid][0] + sP[2][tid][0] + sP[3][tid][0];
            r.y = sP[0][tid][1] + sP[1][tid][1] + sP[2][tid][1] + sP[3][tid][1];
            r.z = sP[0][tid][2] + sP[1][tid][2] + sP[2][tid][2] + sP[3][tid][2];
            r.w = sP[0][tid][3] + sP[1][tid][3] + sP[2][tid][3] + sP[3][tid][3];
            g_node[gn] = r;
        }
    }
}

// ---------------------------------------------------------------------------
// K2: edge scatter — compute gate and store the PROJECTED message.
// 8 edges per thread. Per edge: float4 g_node[src] (du,_,z0,z1), scalar
// g_node[dst].y (dv), then bucket[dst] += entry (w*z0, w*z1).
// ---------------------------------------------------------------------------
__global__ void scatter_kernel(const int* __restrict__ src,
                               const int* __restrict__ dst,
                               const float* __restrict__ b_edge) {
    int t = blockIdx.x * blockDim.x + threadIdx.x;
    if (t * 8 >= N_EDGES) return;
    const int4* s4 = (const int4*)src;
    const int4* d4 = (const int4*)dst;
    int4 sA = s4[2 * t], sB = s4[2 * t + 1];
    int4 dA = d4[2 * t], dB = d4[2 * t + 1];
    float be = b_edge[0];
    const float* nodef = (const float*)g_node;

    // issue all random loads first (MLP 16)
    float4 a0 = g_node[sA.x], a1 = g_node[sA.y], a2 = g_node[sA.z], a3 = g_node[sA.w];
    float4 a4 = g_node[sB.x], a5 = g_node[sB.y], a6 = g_node[sB.z], a7 = g_node[sB.w];
    float v0 = nodef[4 * dA.x + 1], v1 = nodef[4 * dA.y + 1];
    float v2 = nodef[4 * dA.z + 1], v3 = nodef[4 * dA.w + 1];
    float v4 = nodef[4 * dB.x + 1], v5 = nodef[4 * dB.y + 1];
    float v6 = nodef[4 * dB.z + 1], v7 = nodef[4 * dB.w + 1];

    #define GATE(a, v) (1.0f / (1.0f + __expf(-((a).x + (v) + be))))
    float w0 = GATE(a0, v0), w1 = GATE(a1, v1), w2 = GATE(a2, v2), w3 = GATE(a3, v3);
    float w4 = GATE(a4, v4), w5 = GATE(a5, v5), w6 = GATE(a6, v6), w7 = GATE(a7, v7);
    #undef GATE

    int p;
    p = atomicAdd(&g_cnt[dA.x], 1); g_bucket[dA.x * CAP + p] = make_float2(w0 * a0.z, w0 * a0.w);
    p = atomicAdd(&g_cnt[dA.y], 1); g_bucket[dA.y * CAP + p] = make_float2(w1 * a1.z, w1 * a1.w);
    p = atomicAdd(&g_cnt[dA.z], 1); g_bucket[dA.z * CAP + p] = make_float2(w2 * a2.z, w2 * a2.w);
    p = atomicAdd(&g_cnt[dA.w], 1); g_bucket[dA.w * CAP + p] = make_float2(w3 * a3.z, w3 * a3.w);
    p = atomicAdd(&g_cnt[dB.x], 1); g_bucket[dB.x * CAP + p] = make_float2(w4 * a4.z, w4 * a4.w);
    p = atomicAdd(&g_cnt[dB.y], 1); g_bucket[dB.y * CAP + p] = make_float2(w5 * a5.z, w5 * a5.w);
    p = atomicAdd(&g_cnt[dB.z], 1); g_bucket[dB.z * CAP + p] = make_float2(w6 * a6.z, w6 * a6.w);
    p = atomicAdd(&g_cnt[dB.w], 1); g_bucket[dB.w * CAP + p] = make_float2(w7 * a7.z, w7 * a7.w);
}

// ---------------------------------------------------------------------------
// K3: segment sum of projected messages — ONE THREAD PER NODE, purely
// sequential reads of the node's own bucket row (float4 = 2 entries).
// ---------------------------------------------------------------------------
__global__ void agg_out_kernel(const float* __restrict__ b_out,
                               float* __restrict__ out) {
    int n = blockIdx.x * blockDim.x + threadIdx.x;
    if (n >= N_NODES) return;

    int cnt = g_cnt[n];
    float s0 = 0.f, s1 = 0.f;
    const float4* row = (const float4*)&g_bucket[n * CAP];
    int pairs = cnt >> 1;
#pragma unroll 4
    for (int k = 0; k < pairs; k++) {
        float4 v = row[k];
        s0 += v.x + v.z;
        s1 += v.y + v.w;
    }
    if (cnt & 1) {
        float2 v = g_bucket[n * CAP + cnt - 1];
        s0 += v.x;
        s1 += v.y;
    }
    if (cnt == 0) {                  // h_new = h  ->  out = z + b_out
        float4 nd = g_node[n];
        s0 = nd.z;
        s1 = nd.w;
    }
    out[2 * n + 0] = s0 + b_out[0];
    out[2 * n + 1] = s1 + b_out[1];
}

// ---------------------------------------------------------------------------
extern "C" void kernel_launch(void* const* d_in, const int* in_sizes, int n_in,
                              void* d_out, int out_size) {
    const float* feat   = (const float*)d_in[0];
    const int*   src    = (const int*)  d_in[1];
    const int*   dst    = (const int*)  d_in[2];
    const float* W_in   = (const float*)d_in[3];
    const float* b_in   = (const float*)d_in[4];
    const float* W_edge = (const float*)d_in[5];
    const float* b_edge = (const float*)d_in[6];
    const float* W_out  = (const float*)d_in[7];
    const float* b_out  = (const float*)d_in[8];
    float* out = (float*)d_out;

    zero_kernel<<<(N_NODES + 255) / 256, 256>>>();
    input_gemm_kernel<<<(N_NODES + 63) / 64, 256>>>(feat, W_in, b_in, W_edge, W_out);
    scatter_kernel<<<(N_EDGES / 8 + 255) / 256, 256>>>(src, dst, b_edge);
    agg_out_kernel<<<(N_NODES + 255) / 256, 256>>>(b_out, out);
}

// round 13
// speedup vs baseline: 1.9937x; 1.2124x over previous
#include <cuda_runtime.h>
#include <math.h>

#define N_NODES 100000
#define N_EDGES 1600000
#define HID 64

// Scratch (no cudaMalloc allowed).
__device__ float4 g_node[N_NODES];   // (dotu, dotv, z0, z1) per node, 1.6 MB
__device__ float4 g_acc[N_NODES];    // (sum_w*z0, sum_w*z1, deg, pad), 1.6 MB

// ---------------------------------------------------------------------------
// f32x2 helpers (packed dual-fp32 FMA).
// ---------------------------------------------------------------------------
__device__ __forceinline__ unsigned long long pack2(float x, float y) {
    unsigned long long r;
    asm("mov.b64 %0, {%1, %2};" : "=l"(r) : "f"(x), "f"(y));
    return r;
}
__device__ __forceinline__ void unpack2(unsigned long long v, float& x, float& y) {
    asm("mov.b64 {%0, %1}, %2;" : "=f"(x), "=f"(y) : "l"(v));
}
__device__ __forceinline__ void fma2(unsigned long long& acc,
                                     unsigned long long a,
                                     unsigned long long b) {
    asm("fma.rn.f32x2 %0, %1, %2, %0;" : "+l"(acc) : "l"(a), "l"(b));
}

// ---------------------------------------------------------------------------
// K1: h = feat @ W_in + b_in (f32x2 FFMA2, h stays in REGISTERS), fused with
// the four per-node linear functionals:
//   dotu = h·W_edge[0:64], dotv = h·W_edge[64:128],
//   z0 = h·W_out[:,0], z1 = h·W_out[:,1]
// Writes g_node[n] = (dotu, dotv, z0, z1) and zeroes g_acc[n].
// ---------------------------------------------------------------------------
__global__ void input_gemm_kernel(const float* __restrict__ feat,
                                  const float* __restrict__ W_in,
                                  const float* __restrict__ b_in,
                                  const float* __restrict__ W_edge,
                                  const float* __restrict__ W_out) {
    __shared__ __align__(16) float sW[HID * HID];   // W_in, 16 KB
    __shared__ float sB[HID];
    __shared__ float sT[HID][HID + 1];              // transposed feat tile
    __shared__ float sWu[HID], sWv[HID], sWo0[HID], sWo1[HID];
    __shared__ float sP[4][HID][4];                 // per-q partials (du,dv,z0,z1)

    int tid   = threadIdx.x;
    int node0 = blockIdx.x * 64;
    int n     = tid & 63;
    int q     = tid >> 6;
    int j0    = q * 16;

    for (int k = tid; k < HID * HID; k += 256) sW[k] = W_in[k];
    if (tid < HID) {
        sB[tid]   = b_in[tid];
        sWu[tid]  = W_edge[tid];
        sWv[tid]  = W_edge[HID + tid];
        sWo0[tid] = W_out[2 * tid];
        sWo1[tid] = W_out[2 * tid + 1];
    }
    for (int idx = tid; idx < 64 * HID; idx += 256) {
        int nn = idx >> 6, k = idx & 63;
        int gn = node0 + nn;
        sT[k][nn] = (gn < N_NODES) ? feat[gn * HID + k] : 0.0f;
    }
    __syncthreads();

    unsigned long long acc[8];
#pragma unroll
    for (int p = 0; p < 8; p++) acc[p] = pack2(sB[j0 + 2 * p], sB[j0 + 2 * p + 1]);

    const ulonglong2* sW2 = (const ulonglong2*)sW;
#pragma unroll 8
    for (int k = 0; k < HID; k++) {
        float f = sT[k][n];
        unsigned long long ff = pack2(f, f);
        ulonglong2 wA = sW2[k * 16 + q * 4 + 0];
        ulonglong2 wB = sW2[k * 16 + q * 4 + 1];
        ulonglong2 wC = sW2[k * 16 + q * 4 + 2];
        ulonglong2 wD = sW2[k * 16 + q * 4 + 3];
        fma2(acc[0], ff, wA.x); fma2(acc[1], ff, wA.y);
        fma2(acc[2], ff, wB.x); fma2(acc[3], ff, wB.y);
        fma2(acc[4], ff, wC.x); fma2(acc[5], ff, wC.y);
        fma2(acc[6], ff, wD.x); fma2(acc[7], ff, wD.y);
    }

    // per-thread partial functionals from registers
    float hx[16];
#pragma unroll
    for (int p = 0; p < 8; p++) unpack2(acc[p], hx[2 * p], hx[2 * p + 1]);
    float du = 0.f, dv = 0.f, z0 = 0.f, z1 = 0.f;
#pragma unroll
    for (int j = 0; j < 16; j++) {
        float hv = hx[j];
        du = fmaf(hv, sWu[j0 + j],  du);
        dv = fmaf(hv, sWv[j0 + j],  dv);
        z0 = fmaf(hv, sWo0[j0 + j], z0);
        z1 = fmaf(hv, sWo1[j0 + j], z1);
    }
    sP[q][n][0] = du; sP[q][n][1] = dv; sP[q][n][2] = z0; sP[q][n][3] = z1;
    __syncthreads();

    if (tid < 64) {
        int gn = node0 + tid;
        if (gn < N_NODES) {
            float4 r;
            r.x = sP[0][tid][0] + sP[1][tid][0] + sP[2][tid][0] + sP[3][tid][0];
            r.y = sP[0][tid][1] + sP[1][tid][1] + sP[2][tid][1] + sP[3][tid][1];
            r.z = sP[0][tid][2] + sP[1][tid][2] + sP[2][tid][2] + sP[3][tid][2];
            r.w = sP[0][tid][3] + sP[1][tid][3] + sP[2][tid][3] + sP[3][tid][3];
            g_node[gn] = r;
            g_acc[gn]  = make_float4(0.f, 0.f, 0.f, 0.f);   // fused zeroing
        }
    }
}

// ---------------------------------------------------------------------------
// K2: edge scatter — gate + projected message, ONE vector RED per edge:
//   g_acc[dst] += (w*z0, w*z1, 1, 0)
// 8 edges per thread (MLP 16 on the gathers).
// ---------------------------------------------------------------------------
__global__ void scatter_kernel(const int* __restrict__ src,
                               const int* __restrict__ dst,
                               const float* __restrict__ b_edge) {
    int t = blockIdx.x * blockDim.x + threadIdx.x;
    if (t * 8 >= N_EDGES) return;
    const int4* s4 = (const int4*)src;
    const int4* d4 = (const int4*)dst;
    int4 sA = s4[2 * t], sB = s4[2 * t + 1];
    int4 dA = d4[2 * t], dB = d4[2 * t + 1];
    float be = b_edge[0];
    const float* nodef = (const float*)g_node;

    // issue all random loads first (MLP 16)
    float4 a0 = g_node[sA.x], a1 = g_node[sA.y], a2 = g_node[sA.z], a3 = g_node[sA.w];
    float4 a4 = g_node[sB.x], a5 = g_node[sB.y], a6 = g_node[sB.z], a7 = g_node[sB.w];
    float v0 = nodef[4 * dA.x + 1], v1 = nodef[4 * dA.y + 1];
    float v2 = nodef[4 * dA.z + 1], v3 = nodef[4 * dA.w + 1];
    float v4 = nodef[4 * dB.x + 1], v5 = nodef[4 * dB.y + 1];
    float v6 = nodef[4 * dB.z + 1], v7 = nodef[4 * dB.w + 1];

    #define GATE(a, v) (1.0f / (1.0f + __expf(-((a).x + (v) + be))))
    float w0 = GATE(a0, v0), w1 = GATE(a1, v1), w2 = GATE(a2, v2), w3 = GATE(a3, v3);
    float w4 = GATE(a4, v4), w5 = GATE(a5, v5), w6 = GATE(a6, v6), w7 = GATE(a7, v7);
    #undef GATE

    atomicAdd(&g_acc[dA.x], make_float4(w0 * a0.z, w0 * a0.w, 1.0f, 0.0f));
    atomicAdd(&g_acc[dA.y], make_float4(w1 * a1.z, w1 * a1.w, 1.0f, 0.0f));
    atomicAdd(&g_acc[dA.z], make_float4(w2 * a2.z, w2 * a2.w, 1.0f, 0.0f));
    atomicAdd(&g_acc[dA.w], make_float4(w3 * a3.z, w3 * a3.w, 1.0f, 0.0f));
    atomicAdd(&g_acc[dB.x], make_float4(w4 * a4.z, w4 * a4.w, 1.0f, 0.0f));
    atomicAdd(&g_acc[dB.y], make_float4(w5 * a5.z, w5 * a5.w, 1.0f, 0.0f));
    atomicAdd(&g_acc[dB.z], make_float4(w6 * a6.z, w6 * a6.w, 1.0f, 0.0f));
    atomicAdd(&g_acc[dB.w], make_float4(w7 * a7.z, w7 * a7.w, 1.0f, 0.0f));
}

// ---------------------------------------------------------------------------
// K3: out[n] = (deg>0 ? acc.xy : z) + b_out. Fully coalesced, trivial.
// ---------------------------------------------------------------------------
__global__ void out_kernel(const float* __restrict__ b_out,
                           float* __restrict__ out) {
    int n = blockIdx.x * blockDim.x + threadIdx.x;
    if (n >= N_NODES) return;
    float4 a  = g_acc[n];
    float4 nd = g_node[n];
    float s0 = (a.z > 0.f) ? a.x : nd.z;
    float s1 = (a.z > 0.f) ? a.y : nd.w;
    ((float2*)out)[n] = make_float2(s0 + b_out[0], s1 + b_out[1]);
}

// ---------------------------------------------------------------------------
extern "C" void kernel_launch(void* const* d_in, const int* in_sizes, int n_in,
                              void* d_out, int out_size) {
    const float* feat   = (const float*)d_in[0];
    const int*   src    = (const int*)  d_in[1];
    const int*   dst    = (const int*)  d_in[2];
    const float* W_in   = (const float*)d_in[3];
    const float* b_in   = (const float*)d_in[4];
    const float* W_edge = (const float*)d_in[5];
    const float* b_edge = (const float*)d_in[6];
    const float* W_out  = (const float*)d_in[7];
    const float* b_out  = (const float*)d_in[8];
    float* out = (float*)d_out;

    input_gemm_kernel<<<(N_NODES + 63) / 64, 256>>>(feat, W_in, b_in, W_edge, W_out);
    scatter_kernel<<<(N_EDGES / 8 + 255) / 256, 256>>>(src, dst, b_edge);
    out_kernel<<<(N_NODES + 255) / 256, 256>>>(b_out, out);
}